// round 17
// baseline (speedup 1.0000x reference)
#include <cuda_runtime.h>
#include <cuda_fp16.h>
#include <cuda_pipeline.h>
#include <cstdint>

#define BB 4
#define LQ 256
#define LK 256
#define DD 768

// Scratch (no cudaMalloc allowed)
__device__ __half g_qh[BB*LQ*DD];        // q projection (fp16, feeds score)
__device__ __half g_kh[BB*LK*DD];        // k projection (fp16, feeds score)
__device__ __half g_vh[BB*LK*DD];        // v projection (fp16, feeds av)
__device__ __half g_xh[3][BB*LQ*DD];     // fp16 copies of query,key,value inputs
__device__ __half g_wh[3][DD*DD];        // fp16 copies of Wq,Wk,Wv
__device__ float  g_scores[BB*LQ*LK];

// ---- f16x2 helpers ----
__device__ __forceinline__ uint32_t hadd2u(uint32_t a, uint32_t b) {
    uint32_t r;
    asm("add.rn.f16x2 %0, %1, %2;" : "=r"(r) : "r"(a), "r"(b));
    return r;
}
__device__ __forceinline__ uint32_t tanh2u(uint32_t a) {
    uint32_t r;
    asm("tanh.approx.f16x2 %0, %1;" : "=r"(r) : "r"(a));
    return r;
}
__device__ __forceinline__ uint32_t hfma2u(uint32_t a, uint32_t b, uint32_t c) {
    uint32_t r;
    asm("fma.rn.f16x2 %0, %1, %2, %3;" : "=r"(r) : "r"(a), "r"(b), "r"(c));
    return r;
}
__device__ __forceinline__ float2 h22f2(uint32_t h) {
    __half2 hh = *(__half2*)&h;
    return __half22float2(hh);
}

// ---- fp16 mma helpers ----
__device__ __forceinline__ void mma_f16(float& d0, float& d1, float& d2, float& d3,
                                        uint32_t a0, uint32_t a1, uint32_t a2, uint32_t a3,
                                        uint32_t b0, uint32_t b1) {
    asm("mma.sync.aligned.m16n8k16.row.col.f32.f16.f16.f32 "
        "{%0,%1,%2,%3}, {%4,%5,%6,%7}, {%8,%9}, {%0,%1,%2,%3};"
        : "+f"(d0), "+f"(d1), "+f"(d2), "+f"(d3)
        : "r"(a0), "r"(a1), "r"(a2), "r"(a3), "r"(b0), "r"(b1));
}
__device__ __forceinline__ void ldsm_x4(uint32_t& r0, uint32_t& r1, uint32_t& r2, uint32_t& r3,
                                        uint32_t addr) {
    asm volatile("ldmatrix.sync.aligned.m8n8.x4.shared.b16 {%0,%1,%2,%3}, [%4];"
                 : "=r"(r0), "=r"(r1), "=r"(r2), "=r"(r3) : "r"(addr));
}
__device__ __forceinline__ void ldsm_x4_t(uint32_t& r0, uint32_t& r1, uint32_t& r2, uint32_t& r3,
                                          uint32_t addr) {
    asm volatile("ldmatrix.sync.aligned.m8n8.x4.trans.shared.b16 {%0,%1,%2,%3}, [%4];"
                 : "=r"(r0), "=r"(r1), "=r"(r2), "=r"(r3) : "r"(addr));
}

// ---------------------------------------------------------------------------
// Shared-memory layouts
// ---------------------------------------------------------------------------
struct ProjSmem {
    __half As[2][64][40];
    __half Bsm[2][32][136];
};
struct ScoreSmem {
    uint32_t Qh[32][36];
    uint32_t Kt[32][33];
    uint32_t Wsh[32];
};

// ---------------------------------------------------------------------------
// fp32 -> fp16 conversion helper
// ---------------------------------------------------------------------------
__device__ __forceinline__ void cvt_one(const float* __restrict__ src,
                                        __half* __restrict__ dst, int n,
                                        int bx, int t)
{
    const int idx = (bx * 256 + t) * 8;
    if (idx >= n) return;
    float4 a = *(const float4*)(src + idx);
    float4 b = *(const float4*)(src + idx + 4);
    __half2 h0 = __floats2half2_rn(a.x, a.y);
    __half2 h1 = __floats2half2_rn(a.z, a.w);
    __half2 h2 = __floats2half2_rn(b.x, b.y);
    __half2 h3 = __floats2half2_rn(b.z, b.w);
    uint4 o;
    o.x = *(const uint32_t*)&h0;
    o.y = *(const uint32_t*)&h1;
    o.z = *(const uint32_t*)&h2;
    o.w = *(const uint32_t*)&h3;
    *(uint4*)(dst + idx) = o;
}

// cvt for q,k inputs + Wq,Wk. Grid (384, 4).
__global__ __launch_bounds__(256) void cvt_main_kernel(
    const float* __restrict__ xq, const float* __restrict__ xk,
    const float* __restrict__ Wq, const float* __restrict__ Wk)
{
    const int id = blockIdx.y;
    if (id == 0)      cvt_one(xq, g_xh[0], BB*LQ*DD, blockIdx.x, threadIdx.x);
    else if (id == 1) cvt_one(xk, g_xh[1], BB*LQ*DD, blockIdx.x, threadIdx.x);
    else if (id == 2) cvt_one(Wq, g_wh[0], DD*DD,    blockIdx.x, threadIdx.x);
    else              cvt_one(Wk, g_wh[1], DD*DD,    blockIdx.x, threadIdx.x);
}

// cvt for v input + Wv (side stream). Grid (384, 2).
__global__ __launch_bounds__(256) void cvt_v_kernel(
    const float* __restrict__ xv, const float* __restrict__ Wv)
{
    if (blockIdx.y == 0) cvt_one(xv, g_xh[2], BB*LQ*DD, blockIdx.x, threadIdx.x);
    else                 cvt_one(Wv, g_wh[2], DD*DD,    blockIdx.x, threadIdx.x);
}

// ---------------------------------------------------------------------------
// One 64(M)x128(N) fp16-mma projection tile (R13-proven body).
// ---------------------------------------------------------------------------
__device__ __forceinline__ void proj_tile(
    const __half* __restrict__ X, const __half* __restrict__ W,
    const float* __restrict__ bias, __half* __restrict__ Out,
    int m0, int n0, int t, ProjSmem& S)
{
    const int wid  = t >> 5;
    const int lane = t & 31;
    const int wm   = wid & 1;
    const int wn   = wid >> 1;
    const int grp  = lane >> 2;
    const int tig  = lane & 3;

    float acc[2][4][4];
    #pragma unroll
    for (int i = 0; i < 2; i++)
        #pragma unroll
        for (int j = 0; j < 4; j++)
            #pragma unroll
            for (int r = 0; r < 4; r++) acc[i][j][r] = 0.f;

    const int ar = t >> 2, acs = (t & 3) * 8;
    const int br = t >> 3, bcs = (t & 7) * 16;

    const __half* Xp = X + (size_t)(m0 + ar) * DD + acs;
    const __half* Wp = W + (size_t)br * DD + n0 + bcs;

    const int lrow = lane & 15;
    const int lca  = (lane >> 4) * 8;
    const uint32_t a_addr0 =
        (uint32_t)__cvta_generic_to_shared(&S.As[0][wm*32 + lrow][lca]);
    const int brow = ((lane >> 3) & 1) * 8 + (lane & 7);
    const int bcol = (lane >> 4) * 8;
    const uint32_t b_addr0 =
        (uint32_t)__cvta_generic_to_shared(&S.Bsm[0][brow][wn*32 + bcol]);

    __pipeline_memcpy_async(&S.As[0][ar][acs], Xp, 16);
    __pipeline_memcpy_async(&S.Bsm[0][br][bcs],     Wp,     16);
    __pipeline_memcpy_async(&S.Bsm[0][br][bcs + 8], Wp + 8, 16);
    __pipeline_commit();

    for (int k0 = 0; k0 < DD; k0 += 32) {
        const int buf = (k0 >> 5) & 1;
        if (k0 + 32 < DD) {
            const int nb = buf ^ 1;
            __pipeline_memcpy_async(&S.As[nb][ar][acs], Xp + k0 + 32, 16);
            const __half* wpn = Wp + (size_t)(k0 + 32) * DD;
            __pipeline_memcpy_async(&S.Bsm[nb][br][bcs],     wpn,     16);
            __pipeline_memcpy_async(&S.Bsm[nb][br][bcs + 8], wpn + 8, 16);
            __pipeline_commit();
            __pipeline_wait_prior(1);
        } else {
            __pipeline_wait_prior(0);
        }
        __syncthreads();

        #pragma unroll
        for (int ks = 0; ks < 2; ks++) {
            uint32_t a[2][4];
            #pragma unroll
            for (int mi = 0; mi < 2; mi++) {
                const uint32_t ad = a_addr0 + (uint32_t)(buf*5120 + mi*1280 + ks*32);
                ldsm_x4(a[mi][0], a[mi][1], a[mi][2], a[mi][3], ad);
            }
            uint32_t b[4][2];
            #pragma unroll
            for (int p = 0; p < 2; p++) {
                const uint32_t bd = b_addr0 + (uint32_t)(buf*8704 + ks*4352 + p*32);
                ldsm_x4_t(b[p*2][0], b[p*2][1], b[p*2+1][0], b[p*2+1][1], bd);
            }
            #pragma unroll
            for (int mi = 0; mi < 2; mi++)
                #pragma unroll
                for (int ni = 0; ni < 4; ni++)
                    mma_f16(acc[mi][ni][0], acc[mi][ni][1], acc[mi][ni][2], acc[mi][ni][3],
                            a[mi][0], a[mi][1], a[mi][2], a[mi][3],
                            b[ni][0], b[ni][1]);
        }
        __syncthreads();
    }

    #pragma unroll
    for (int mi = 0; mi < 2; mi++) {
        #pragma unroll
        for (int ni = 0; ni < 4; ni++) {
            const int col = n0 + wn*32 + ni*8 + 2*tig;
            const float b0 = bias[col], b1 = bias[col+1];
            const int r0 = m0 + wm*32 + mi*16 + grp;
            const int r1 = r0 + 8;
            __half2 lo = __floats2half2_rn(acc[mi][ni][0] + b0, acc[mi][ni][1] + b1);
            __half2 hi = __floats2half2_rn(acc[mi][ni][2] + b0, acc[mi][ni][3] + b1);
            *(__half2*)&Out[(size_t)r0 * DD + col] = lo;
            *(__half2*)&Out[(size_t)r1 * DD + col] = hi;
        }
    }
}

// q,k projections. Grid (6, 16, 2).
__global__ __launch_bounds__(256) void proj_qk_kernel(
    const float* __restrict__ bq, const float* __restrict__ bk)
{
    __shared__ ProjSmem S;
    const int z = blockIdx.z;
    proj_tile(g_xh[z], g_wh[z], (z == 0) ? bq : bk, (z == 0) ? g_qh : g_kh,
              blockIdx.y * 64, blockIdx.x * 128, threadIdx.x, S);
}

// v projection (side stream, runs under score). Grid (6, 16).
__global__ __launch_bounds__(256) void proj_v_kernel(const float* __restrict__ bv)
{
    __shared__ ProjSmem S;
    proj_tile(g_xh[2], g_wh[2], bv, g_vh,
              blockIdx.y * 64, blockIdx.x * 128, threadIdx.x, S);
}

// ---------------------------------------------------------------------------
// Scores via tanh.approx.f16x2 (R13-proven, ~40.6us). 32x32 tile, 256 thr.
// Grid (8,8,4).
// ---------------------------------------------------------------------------
__global__ __launch_bounds__(256) void score_kernel(const float* __restrict__ Ws,
                                                    const float* __restrict__ bsp)
{
    __shared__ ScoreSmem S;
    const int bz = blockIdx.z;
    const int q0 = blockIdx.y * 32;
    const int k0 = blockIdx.x * 32;

    const int t  = threadIdx.x;
    const int tx = t & 15, ty = t >> 4;

    float acc00 = 0.f, acc01 = 0.f, acc10 = 0.f, acc11 = 0.f;

    const __half* qb = g_qh + ((size_t)bz*LQ + q0) * DD;
    const __half* kb = g_kh + ((size_t)bz*LK + k0) * DD;

    const int lr = t >> 3;
    const int lc = t & 7;

    for (int d0 = 0; d0 < DD; d0 += 64) {
        uint4 qv = *(const uint4*)(qb + (size_t)lr*DD + d0 + lc*8);
        *(uint4*)&S.Qh[lr][lc*4] = qv;
        uint4 kv = *(const uint4*)(kb + (size_t)lr*DD + d0 + lc*8);
        S.Kt[lc*4+0][lr] = kv.x;
        S.Kt[lc*4+1][lr] = kv.y;
        S.Kt[lc*4+2][lr] = kv.z;
        S.Kt[lc*4+3][lr] = kv.w;
        if (t < 32) {
            float2 w = *(const float2*)&Ws[d0 + t*2];
            __half2 wh = __floats2half2_rn(w.x, w.y);
            S.Wsh[t] = *(const uint32_t*)&wh;
        }
        __syncthreads();

        #pragma unroll
        for (int g = 0; g < 8; g++) {
            uint32_t p00 = 0u, p01 = 0u, p10 = 0u, p11 = 0u;
            #pragma unroll
            for (int u = 0; u < 4; u++) {
                const int dp = g*4 + u;
                const uint32_t w2 = S.Wsh[dp];
                const uint32_t qa = S.Qh[ty*2+0][dp];
                const uint32_t qc = S.Qh[ty*2+1][dp];
                const uint32_t ka = S.Kt[dp][tx*2+0];
                const uint32_t kc = S.Kt[dp][tx*2+1];
                p00 = hfma2u(w2, tanh2u(hadd2u(qa, ka)), p00);
                p01 = hfma2u(w2, tanh2u(hadd2u(qa, kc)), p01);
                p10 = hfma2u(w2, tanh2u(hadd2u(qc, ka)), p10);
                p11 = hfma2u(w2, tanh2u(hadd2u(qc, kc)), p11);
            }
            float2 f0 = h22f2(p00); acc00 += f0.x + f0.y;
            float2 f1 = h22f2(p01); acc01 += f1.x + f1.y;
            float2 f2 = h22f2(p10); acc10 += f2.x + f2.y;
            float2 f3 = h22f2(p11); acc11 += f3.x + f3.y;
        }
        __syncthreads();
    }

    const float bsv = *bsp;
    float* sp = g_scores + ((size_t)bz*LQ + q0) * LK + k0;
    sp[(ty*2+0)*LK + tx*2+0] = acc00 + bsv;
    sp[(ty*2+0)*LK + tx*2+1] = acc01 + bsv;
    sp[(ty*2+1)*LK + tx*2+0] = acc10 + bsv;
    sp[(ty*2+1)*LK + tx*2+1] = acc11 + bsv;
}

// ---------------------------------------------------------------------------
// Row softmax over LK=256. One block (256 threads) per (b,q) row.
// ---------------------------------------------------------------------------
__global__ __launch_bounds__(256) void softmax_kernel(float* __restrict__ wout)
{
    const int row = blockIdx.x;
    const int t   = threadIdx.x;
    __shared__ float red[8];

    const float v = g_scores[(size_t)row*LK + t];

    float m = v;
    #pragma unroll
    for (int o = 16; o > 0; o >>= 1) m = fmaxf(m, __shfl_xor_sync(0xffffffffu, m, o));
    if ((t & 31) == 0) red[t >> 5] = m;
    __syncthreads();
    float mx = red[0];
    #pragma unroll
    for (int i = 1; i < 8; i++) mx = fmaxf(mx, red[i]);
    __syncthreads();

    const float e = __expf(v - mx);
    float s = e;
    #pragma unroll
    for (int o = 16; o > 0; o >>= 1) s += __shfl_xor_sync(0xffffffffu, s, o);
    if ((t & 31) == 0) red[t >> 5] = s;
    __syncthreads();
    float sum = 0.f;
    #pragma unroll
    for (int i = 0; i < 8; i++) sum += red[i];

    wout[(size_t)row*LK + t] = e * (1.0f / sum);
}

// ---------------------------------------------------------------------------
// attended = weights @ v via fp16 mma (R13-proven, ~13us). Grid (6,8,4).
// ---------------------------------------------------------------------------
__global__ __launch_bounds__(256) void av_kernel(const float* __restrict__ wts,
                                                 float* __restrict__ out)
{
    const int b  = blockIdx.z;
    const int q0 = blockIdx.y * 32;
    const int d0 = blockIdx.x * 128;

    __shared__ __half As[2][32][40];
    __shared__ __half Bsm[2][32][136];

    const int t    = threadIdx.x;
    const int wid  = t >> 5;
    const int lane = t & 31;
    const int grp  = lane >> 2;
    const int tig  = lane & 3;

    float acc[2][2][4];
    #pragma unroll
    for (int i = 0; i < 2; i++)
        #pragma unroll
        for (int j = 0; j < 2; j++)
            #pragma unroll
            for (int r = 0; r < 4; r++) acc[i][j][r] = 0.f;

    const int ar = t >> 3, ac4 = (t & 7) * 4;
    const int br = t >> 3, bcs = (t & 7) * 16;

    const float*  Ap = wts + ((size_t)b*LQ + q0 + ar) * LK + ac4;
    const __half* Bp = g_vh + ((size_t)b*LK + br) * DD + d0 + bcs;

    const int lrow = lane & 15;
    const int lca  = (lane >> 4) * 8;
    const uint32_t a_addr0 = (uint32_t)__cvta_generic_to_shared(&As[0][lrow][lca]);
    const int brow = ((lane >> 3) & 1) * 8 + (lane & 7);
    const int bcol = (lane >> 4) * 8;
    const uint32_t b_addr0 =
        (uint32_t)__cvta_generic_to_shared(&Bsm[0][brow][wid*16 + bcol]);

    float4 pa = *(const float4*)(Ap);
    __pipeline_memcpy_async(&Bsm[0][br][bcs],     Bp,     16);
    __pipeline_memcpy_async(&Bsm[0][br][bcs + 8], Bp + 8, 16);
    __pipeline_commit();

    for (int j0 = 0; j0 < LK; j0 += 32) {
        const int buf = (j0 >> 5) & 1;
        {
            __half2 h0 = __floats2half2_rn(pa.x, pa.y);
            __half2 h1 = __floats2half2_rn(pa.z, pa.w);
            uint2 o = { *(const uint32_t*)&h0, *(const uint32_t*)&h1 };
            *(uint2*)&As[buf][ar][ac4] = o;
        }
        if (j0 + 32 < LK) {
            const int nb = buf ^ 1;
            pa = *(const float4*)(Ap + j0 + 32);
            const __half* bpn = Bp + (size_t)(j0 + 32) * DD;
            __pipeline_memcpy_async(&Bsm[nb][br][bcs],     bpn,     16);
            __pipeline_memcpy_async(&Bsm[nb][br][bcs + 8], bpn + 8, 16);
            __pipeline_commit();
            __pipeline_wait_prior(1);
        } else {
            __pipeline_wait_prior(0);
        }
        __syncthreads();

        #pragma unroll
        for (int ks = 0; ks < 2; ks++) {
            uint32_t a[2][4];
            #pragma unroll
            for (int mi = 0; mi < 2; mi++) {
                const uint32_t ad = a_addr0 + (uint32_t)(buf*2560 + mi*1280 + ks*32);
                ldsm_x4(a[mi][0], a[mi][1], a[mi][2], a[mi][3], ad);
            }
            uint32_t bf[2][2];
            {
                const uint32_t bd = b_addr0 + (uint32_t)(buf*8704 + ks*4352);
                ldsm_x4_t(bf[0][0], bf[0][1], bf[1][0], bf[1][1], bd);
            }
            #pragma unroll
            for (int mi = 0; mi < 2; mi++)
                #pragma unroll
                for (int ni = 0; ni < 2; ni++)
                    mma_f16(acc[mi][ni][0], acc[mi][ni][1], acc[mi][ni][2], acc[mi][ni][3],
                            a[mi][0], a[mi][1], a[mi][2], a[mi][3],
                            bf[ni][0], bf[ni][1]);
        }
        __syncthreads();
    }

    #pragma unroll
    for (int mi = 0; mi < 2; mi++) {
        #pragma unroll
        for (int ni = 0; ni < 2; ni++) {
            const int col = d0 + wid*16 + ni*8 + 2*tig;
            const int r0  = q0 + mi*16 + grp;
            const int r1  = r0 + 8;
            float2 lo = { acc[mi][ni][0], acc[mi][ni][1] };
            float2 hi = { acc[mi][ni][2], acc[mi][ni][3] };
            *(float2*)&out[((size_t)b*LQ + r0) * DD + col] = lo;
            *(float2*)&out[((size_t)b*LQ + r1) * DD + col] = hi;
        }
    }
}

// ---------------------------------------------------------------------------
extern "C" void kernel_launch(void* const* d_in, const int* in_sizes, int n_in,
                              void* d_out, int out_size)
{
    const float* query = (const float*)d_in[0];
    const float* key   = (const float*)d_in[1];
    const float* value = (const float*)d_in[2];
    const float* Wq    = (const float*)d_in[3];
    const float* bq    = (const float*)d_in[4];
    const float* Wk    = (const float*)d_in[5];
    const float* bk    = (const float*)d_in[6];
    const float* Wv    = (const float*)d_in[7];
    const float* bv    = (const float*)d_in[8];
    const float* Ws    = (const float*)d_in[9];
    const float* bs    = (const float*)d_in[10];

    float* att = (float*)d_out;                  // [B,LQ,D]
    float* wts = att + (size_t)BB * LQ * DD;     // [B,LQ,LK]

    // side stream for the v-chain (fresh per call; not destroyed — destroying
    // a stream that is part of an active capture is illegal)
    cudaStream_t s2;
    cudaStreamCreateWithFlags(&s2, cudaStreamNonBlocking);
    cudaEvent_t evQK, evV;
    cudaEventCreateWithFlags(&evQK, cudaEventDisableTiming);
    cudaEventCreateWithFlags(&evV,  cudaEventDisableTiming);

    // main chain part 1: cvt(q,k,Wq,Wk) -> proj_qk
    cvt_main_kernel<<<dim3(384, 4), 256>>>(query, key, Wq, Wk);
    proj_qk_kernel<<<dim3(DD/128, (BB*LQ)/64, 2), 256>>>(bq, bk);

    // fork AFTER proj_qk: side v-chain (tensor) runs concurrently with
    // score (MUFU) — complementary pipes, not contention.
    cudaEventRecord(evQK, 0);
    cudaStreamWaitEvent(s2, evQK, 0);
    cvt_v_kernel<<<dim3(384, 2), 256, 0, s2>>>(value, Wv);
    proj_v_kernel<<<dim3(DD/128, (BB*LQ)/64), 256, 0, s2>>>(bv);
    cudaEventRecord(evV, s2);

    // main chain part 2: score -> softmax (overlapped by side chain)
    score_kernel<<<dim3(LK/32, LQ/32, BB), 256>>>(Ws, bs);
    softmax_kernel<<<BB*LQ, 256>>>(wts);

    // join: av needs proj_v (side) + softmax (main)
    cudaStreamWaitEvent(0, evV, 0);
    av_kernel<<<dim3(DD/128, LQ/32, BB), 256>>>(wts, att);
}